// round 3
// baseline (speedup 1.0000x reference)
#include <cuda_runtime.h>
#include <math.h>

// ---------------- problem constants ----------------
#define BATCH   2
#define SEQ     8192
#define NTOK    (BATCH*SEQ)        // 16384
#define DMODEL  2048
#define NQKV    6144               // H*DQK*2 + H*DV
#define NHEAD   16
#define DHEAD   128
#define NCHUNK  64                 // SEQ / 128
#define CHUNKL  128
#define QK_SCALE 0.08838834764831845f   // 1/sqrt(128)

#define TP 132   // shared tile pitch (16 x 128 tiles)
#define APITCH 129

// ---------------- device scratch (no cudaMalloc allowed) ----------------
__device__ float g_qkv[(size_t)NTOK * NQKV];                       // 402 MB
__device__ float g_qe [(size_t)NTOK * DMODEL];                     // 134 MB
__device__ float g_ke [(size_t)NTOK * DMODEL];                     // 134 MB (already * QK_SCALE)
__device__ float g_st [(size_t)BATCH * NHEAD * NCHUNK * 128 * 128];// G, then entering-states (in-place scan)
__device__ float g_y  [(size_t)NTOK * DMODEL];                     // normalized attn output

__device__ __forceinline__ float head_slope(int h) {
    // matches reference: -log(1 - 2^(-5-h)) in fp32
    return -logf(1.0f - exp2f(-5.0f - (float)h));
}

// ---------------- generic NT GEMM: C[m,n] = scale * (sum_k A[m,k]*B[n,k] + bias[n]) ----------
// A: M x K row-major (lda), B: N x K row-major (ldb), C: M x N (ldc). M,N mult of 128, K mult of 16.
__global__ __launch_bounds__(256)
void gemm_nt_kernel(const float* __restrict__ A, int lda,
                    const float* __restrict__ B, int ldb,
                    float* __restrict__ C, int ldc,
                    int K,
                    const float* __restrict__ bias, float scale)
{
    __shared__ float As[16][TP];
    __shared__ float Bs[16][TP];
    const int tid = threadIdx.x;
    const int tx = tid & 15;
    const int ty = tid >> 4;
    const int n0 = blockIdx.x * 128;
    const int m0 = blockIdx.y * 128;

    float acc[8][8];
#pragma unroll
    for (int i = 0; i < 8; i++)
#pragma unroll
        for (int j = 0; j < 8; j++) acc[i][j] = 0.0f;

    for (int k0 = 0; k0 < K; k0 += 16) {
#pragma unroll
        for (int it = 0; it < 2; it++) {
            int f   = tid + it * 256;
            int row = f >> 2;          // 0..127
            int kq  = (f & 3) * 4;     // 0,4,8,12
            float4 av = *(const float4*)(A + (size_t)(m0 + row) * lda + k0 + kq);
            As[kq + 0][row] = av.x; As[kq + 1][row] = av.y;
            As[kq + 2][row] = av.z; As[kq + 3][row] = av.w;
            float4 bv = *(const float4*)(B + (size_t)(n0 + row) * ldb + k0 + kq);
            Bs[kq + 0][row] = bv.x; Bs[kq + 1][row] = bv.y;
            Bs[kq + 2][row] = bv.z; Bs[kq + 3][row] = bv.w;
        }
        __syncthreads();
#pragma unroll
        for (int kk = 0; kk < 16; kk++) {
            float a[8], b[8];
#pragma unroll
            for (int u = 0; u < 8; u++) a[u] = As[kk][ty * 8 + u];
#pragma unroll
            for (int u = 0; u < 8; u++) b[u] = Bs[kk][tx * 8 + u];
#pragma unroll
            for (int i = 0; i < 8; i++)
#pragma unroll
                for (int j = 0; j < 8; j++)
                    acc[i][j] = fmaf(a[i], b[j], acc[i][j]);
        }
        __syncthreads();
    }

    float bv[8];
#pragma unroll
    for (int j = 0; j < 8; j++) bv[j] = bias ? bias[n0 + tx * 8 + j] : 0.0f;

#pragma unroll
    for (int i = 0; i < 8; i++) {
        float* crow = C + (size_t)(m0 + ty * 8 + i) * ldc + n0 + tx * 8;
        float4 o1, o2;
        o1.x = scale * (acc[i][0] + bv[0]); o1.y = scale * (acc[i][1] + bv[1]);
        o1.z = scale * (acc[i][2] + bv[2]); o1.w = scale * (acc[i][3] + bv[3]);
        o2.x = scale * (acc[i][4] + bv[4]); o2.y = scale * (acc[i][5] + bv[5]);
        o2.z = scale * (acc[i][6] + bv[6]); o2.w = scale * (acc[i][7] + bv[7]);
        *(float4*)(crow + 0) = o1;
        *(float4*)(crow + 4) = o2;
    }
}

// ---------------- per-chunk KV outer product: G[d,e] = sum_j k[j,d]*kdecay[j]*v[j,e] ----------
__global__ __launch_bounds__(256)
void chunk_kv_kernel()
{
    __shared__ float Ks[16][TP];
    __shared__ float Vs[16][TP];
    const int c = blockIdx.x, h = blockIdx.y, b = blockIdx.z;
    const int tid = threadIdx.x;
    const int tx = tid & 15, ty = tid >> 4;
    const float s = head_slope(h);

    const float* kbase = g_ke  + ((size_t)(b * SEQ + c * CHUNKL)) * DMODEL + h * DHEAD;
    const float* vbase = g_qkv + ((size_t)(b * SEQ + c * CHUNKL)) * NQKV  + 4096 + h * DHEAD;

    float acc[8][8];
#pragma unroll
    for (int i = 0; i < 8; i++)
#pragma unroll
        for (int j = 0; j < 8; j++) acc[i][j] = 0.0f;

    for (int j0 = 0; j0 < CHUNKL; j0 += 16) {
#pragma unroll
        for (int it = 0; it < 2; it++) {
            int f   = tid + it * 256;
            int row = f >> 5;          // 0..15
            int c4  = (f & 31) * 4;    // 0..124
            int j   = j0 + row;
            float kd = expf(-s * (float)(CHUNKL - 1 - j));
            float4 kv = *(const float4*)(kbase + (size_t)j * DMODEL + c4);
            kv.x *= kd; kv.y *= kd; kv.z *= kd; kv.w *= kd;
            *(float4*)&Ks[row][c4] = kv;
            float4 vv = *(const float4*)(vbase + (size_t)j * NQKV + c4);
            *(float4*)&Vs[row][c4] = vv;
        }
        __syncthreads();
#pragma unroll
        for (int kk = 0; kk < 16; kk++) {
            float a[8], bb[8];
#pragma unroll
            for (int u = 0; u < 8; u++) a[u]  = Ks[kk][ty * 8 + u];
#pragma unroll
            for (int u = 0; u < 8; u++) bb[u] = Vs[kk][tx * 8 + u];
#pragma unroll
            for (int i = 0; i < 8; i++)
#pragma unroll
                for (int j = 0; j < 8; j++)
                    acc[i][j] = fmaf(a[i], bb[j], acc[i][j]);
        }
        __syncthreads();
    }

    float* gout = g_st + ((size_t)((b * NHEAD + h) * NCHUNK + c)) * (128 * 128);
#pragma unroll
    for (int i = 0; i < 8; i++) {
        float* row = gout + (size_t)(ty * 8 + i) * 128 + tx * 8;
        *(float4*)(row + 0) = make_float4(acc[i][0], acc[i][1], acc[i][2], acc[i][3]);
        *(float4*)(row + 4) = make_float4(acc[i][4], acc[i][5], acc[i][6], acc[i][7]);
    }
}

// ---------------- in-place scan over chunks: buffer becomes entering-state per chunk ----------
// grid: x = 16384/256 element blocks, y = b*H+h
__global__ __launch_bounds__(256)
void scan_kernel()
{
    const int bh = blockIdx.y;
    const int h  = bh & (NHEAD - 1);
    const float s   = head_slope(h);
    const float lam = expf(-s * (float)CHUNKL);
    const int e = blockIdx.x * 256 + threadIdx.x;   // 0..16383
    float* base = g_st + (size_t)bh * NCHUNK * (128 * 128) + e;
    float S = 0.0f;
#pragma unroll 4
    for (int c = 0; c < NCHUNK; c++) {
        float g = base[(size_t)c * (128 * 128)];
        base[(size_t)c * (128 * 128)] = S;
        S = fmaf(lam, S, g);
    }
}

// ---------------- per-chunk output + fused per-head LayerNorm ----------
// O = (q k^T * mask) v + (q * qdecay) S_enter ; then LN over e (128) per (token,head)
__global__ __launch_bounds__(256)
void chunk_out_kernel()
{
    extern __shared__ float sm[];
    float* Ash = sm;                         // [128][APITCH]  stored transposed: Ash[j*APITCH + i]
    float* T1  = sm + 128 * APITCH;          // [16][TP]
    float* T2  = T1 + 16 * TP;               // [16][TP]

    const int c = blockIdx.x, h = blockIdx.y, b = blockIdx.z;
    const int tid = threadIdx.x;
    const int tx = tid & 15, ty = tid >> 4;
    const float s = head_slope(h);

    const size_t tok0 = (size_t)(b * SEQ + c * CHUNKL);
    const float* qbase = g_qe  + tok0 * DMODEL + h * DHEAD;
    const float* kbase = g_ke  + tok0 * DMODEL + h * DHEAD;
    const float* vbase = g_qkv + tok0 * NQKV  + 4096 + h * DHEAD;
    const float* Sbase = g_st  + ((size_t)((b * NHEAD + h) * NCHUNK + c)) * (128 * 128);

    // ---- phase 1: A = q k^T (k already has QK_SCALE folded in) ----
    float acc[8][8];
#pragma unroll
    for (int i = 0; i < 8; i++)
#pragma unroll
        for (int j = 0; j < 8; j++) acc[i][j] = 0.0f;

    for (int d0 = 0; d0 < DHEAD; d0 += 16) {
#pragma unroll
        for (int it = 0; it < 2; it++) {
            int f   = tid + it * 256;
            int row = f >> 2;
            int kq  = (f & 3) * 4;
            float4 qv = *(const float4*)(qbase + (size_t)row * DMODEL + d0 + kq);
            T1[(kq + 0) * TP + row] = qv.x; T1[(kq + 1) * TP + row] = qv.y;
            T1[(kq + 2) * TP + row] = qv.z; T1[(kq + 3) * TP + row] = qv.w;
            float4 kv = *(const float4*)(kbase + (size_t)row * DMODEL + d0 + kq);
            T2[(kq + 0) * TP + row] = kv.x; T2[(kq + 1) * TP + row] = kv.y;
            T2[(kq + 2) * TP + row] = kv.z; T2[(kq + 3) * TP + row] = kv.w;
        }
        __syncthreads();
#pragma unroll
        for (int kk = 0; kk < 16; kk++) {
            float a[8], bb[8];
#pragma unroll
            for (int u = 0; u < 8; u++) a[u]  = T1[kk * TP + ty * 8 + u];
#pragma unroll
            for (int u = 0; u < 8; u++) bb[u] = T2[kk * TP + tx * 8 + u];
#pragma unroll
            for (int i = 0; i < 8; i++)
#pragma unroll
                for (int j = 0; j < 8; j++)
                    acc[i][j] = fmaf(a[i], bb[j], acc[i][j]);
        }
        __syncthreads();
    }

    // mask + store A transposed into shared: Ash[j][i]
#pragma unroll
    for (int jj = 0; jj < 8; jj++) {
#pragma unroll
        for (int ii = 0; ii < 8; ii++) {
            int i = ty * 8 + ii, j = tx * 8 + jj;
            float v = (i >= j) ? acc[ii][jj] * expf(-s * (float)(i - j)) : 0.0f;
            Ash[j * APITCH + i] = v;
        }
    }
    __syncthreads();

    // ---- phase 2a: intra = A @ v ----
    float accO[8][8];
#pragma unroll
    for (int i = 0; i < 8; i++)
#pragma unroll
        for (int j = 0; j < 8; j++) accO[i][j] = 0.0f;

    for (int j0 = 0; j0 < CHUNKL; j0 += 16) {
#pragma unroll
        for (int it = 0; it < 2; it++) {
            int f   = tid + it * 256;
            int row = f >> 5;
            int c4  = (f & 31) * 4;
            float4 vv = *(const float4*)(vbase + (size_t)(j0 + row) * NQKV + c4);
            *(float4*)&T1[row * TP + c4] = vv;
        }
        __syncthreads();
#pragma unroll
        for (int kk = 0; kk < 16; kk++) {
            float a[8], bb[8];
#pragma unroll
            for (int u = 0; u < 8; u++) a[u]  = Ash[(j0 + kk) * APITCH + ty * 8 + u];
#pragma unroll
            for (int u = 0; u < 8; u++) bb[u] = T1[kk * TP + tx * 8 + u];
#pragma unroll
            for (int i = 0; i < 8; i++)
#pragma unroll
                for (int j = 0; j < 8; j++)
                    accO[i][j] = fmaf(a[i], bb[j], accO[i][j]);
        }
        __syncthreads();
    }

    // ---- phase 2b: inter = q @ S_enter (qdecay applied afterwards per row) ----
    float acc2[8][8];
#pragma unroll
    for (int i = 0; i < 8; i++)
#pragma unroll
        for (int j = 0; j < 8; j++) acc2[i][j] = 0.0f;

    for (int d0 = 0; d0 < DHEAD; d0 += 16) {
#pragma unroll
        for (int it = 0; it < 2; it++) {
            int f   = tid + it * 256;
            int row = f >> 2;
            int kq  = (f & 3) * 4;
            float4 qv = *(const float4*)(qbase + (size_t)row * DMODEL + d0 + kq);
            T1[(kq + 0) * TP + row] = qv.x; T1[(kq + 1) * TP + row] = qv.y;
            T1[(kq + 2) * TP + row] = qv.z; T1[(kq + 3) * TP + row] = qv.w;
        }
#pragma unroll
        for (int it = 0; it < 2; it++) {
            int f   = tid + it * 256;
            int row = f >> 5;
            int c4  = (f & 31) * 4;
            float4 sv = *(const float4*)(Sbase + (size_t)(d0 + row) * 128 + c4);
            *(float4*)&T2[row * TP + c4] = sv;
        }
        __syncthreads();
#pragma unroll
        for (int kk = 0; kk < 16; kk++) {
            float a[8], bb[8];
#pragma unroll
            for (int u = 0; u < 8; u++) a[u]  = T1[kk * TP + ty * 8 + u];
#pragma unroll
            for (int u = 0; u < 8; u++) bb[u] = T2[kk * TP + tx * 8 + u];
#pragma unroll
            for (int i = 0; i < 8; i++)
#pragma unroll
                for (int j = 0; j < 8; j++)
                    acc2[i][j] = fmaf(a[i], bb[j], acc2[i][j]);
        }
        __syncthreads();
    }

    // ---- combine + fused LayerNorm over e (the 128 cols of this block) ----
    float vals[8][8];
#pragma unroll
    for (int ii = 0; ii < 8; ii++) {
        float qd = expf(-s * (float)(ty * 8 + ii + 1));
#pragma unroll
        for (int jj = 0; jj < 8; jj++)
            vals[ii][jj] = accO[ii][jj] + qd * acc2[ii][jj];
    }

    // partial row sums into T1 (sum) / T2 (sumsq): [row][tx]
#pragma unroll
    for (int ii = 0; ii < 8; ii++) {
        float ps = 0.0f, pq = 0.0f;
#pragma unroll
        for (int jj = 0; jj < 8; jj++) { float v = vals[ii][jj]; ps += v; pq += v * v; }
        T1[(ty * 8 + ii) * 16 + tx] = ps;
        T2[(ty * 8 + ii) * 16 + tx] = pq;
    }
    __syncthreads();

    if (tid < 128) {
        float s1 = 0.0f, s2 = 0.0f;
#pragma unroll
        for (int t = 0; t < 16; t++) { s1 += T1[tid * 16 + t]; s2 += T2[tid * 16 + t]; }
        float mu  = s1 * (1.0f / 128.0f);
        float var = s2 * (1.0f / 128.0f) - mu * mu;
        Ash[tid]       = mu;
        Ash[128 + tid] = rsqrtf(var + 1e-5f);
    }
    __syncthreads();

    float* obase = g_y + tok0 * DMODEL + h * DHEAD;
#pragma unroll
    for (int ii = 0; ii < 8; ii++) {
        int i = ty * 8 + ii;
        float mu = Ash[i], rs = Ash[128 + i];
        float* row = obase + (size_t)i * DMODEL + tx * 8;
        *(float4*)(row + 0) = make_float4((vals[ii][0] - mu) * rs, (vals[ii][1] - mu) * rs,
                                          (vals[ii][2] - mu) * rs, (vals[ii][3] - mu) * rs);
        *(float4*)(row + 4) = make_float4((vals[ii][4] - mu) * rs, (vals[ii][5] - mu) * rs,
                                          (vals[ii][6] - mu) * rs, (vals[ii][7] - mu) * rs);
    }
}

// ---------------- host launcher ----------------
extern "C" void kernel_launch(void* const* d_in, const int* in_sizes, int n_in,
                              void* d_out, int out_size)
{
    (void)in_sizes; (void)n_in; (void)out_size;
    const float* x       = (const float*)d_in[0];
    const float* W_in    = (const float*)d_in[1];
    const float* W_embed = (const float*)d_in[2];
    const float* b_embed = (const float*)d_in[3];
    const float* W_out   = (const float*)d_in[4];
    float* out = (float*)d_out;

    float *qkv, *qe, *ke, *y;
    cudaGetSymbolAddress((void**)&qkv, g_qkv);
    cudaGetSymbolAddress((void**)&qe,  g_qe);
    cudaGetSymbolAddress((void**)&ke,  g_ke);
    cudaGetSymbolAddress((void**)&y,   g_y);

    const int smem_k5 = (128 * APITCH + 2 * 16 * TP) * 4;   // 82944 B
    cudaFuncSetAttribute(chunk_out_kernel, cudaFuncAttributeMaxDynamicSharedMemorySize, smem_k5);

    // 1) qkv = x @ W_in^T                 (16384 x 6144 x 2048)
    gemm_nt_kernel<<<dim3(NQKV / 128, NTOK / 128), 256>>>(
        x, DMODEL, W_in, DMODEL, qkv, NQKV, DMODEL, nullptr, 1.0f);

    // 2) q_embed = qkv[:, 0:2048] @ W_embed^T + b
    gemm_nt_kernel<<<dim3(DMODEL / 128, NTOK / 128), 256>>>(
        qkv, NQKV, W_embed, DMODEL, qe, DMODEL, DMODEL, b_embed, 1.0f);

    // 3) k_embed = (qkv[:, 2048:4096] @ W_embed^T + b) * QK_SCALE
    gemm_nt_kernel<<<dim3(DMODEL / 128, NTOK / 128), 256>>>(
        qkv + 2048, NQKV, W_embed, DMODEL, ke, DMODEL, DMODEL, b_embed, QK_SCALE);

    // 4) per-chunk KV products
    chunk_kv_kernel<<<dim3(NCHUNK, NHEAD, BATCH), 256>>>();

    // 5) state scan (in-place: G -> entering states)
    scan_kernel<<<dim3(128 * 128 / 256, BATCH * NHEAD), 256>>>();

    // 6) per-chunk output + fused LayerNorm
    chunk_out_kernel<<<dim3(NCHUNK, NHEAD, BATCH), 256, smem_k5>>>();

    // 7) out = y @ W_out^T
    gemm_nt_kernel<<<dim3(DMODEL / 128, NTOK / 128), 256>>>(
        y, DMODEL, W_out, DMODEL, out, DMODEL, DMODEL, nullptr, 1.0f);
}